// round 8
// baseline (speedup 1.0000x reference)
#include <cuda_runtime.h>
#include <cooperative_groups.h>

namespace cg = cooperative_groups;

#define BATCH   64
#define NGT     1024
#define MPRED   2048
#define THRESH2 256.0f    // 16.0^2
#define GDIM    32        // 32x32 grid of 16px cells (512 / 16)
#define NCELL   (GDIM * GDIM)

// Cluster of 2 CTAs (1024 threads) per batch; grid = 128. Each CTA bins the
// batch's 1024 gts AND its 1024 preds (rank r -> preds [r*1024, ...)) into a
// 32x32 cell grid via ONE concatenated 2048-element prefix scan
// ([gt_counts | pred_counts]; since sum(gt_counts) = 1024, s_off[1024] = 1024
// is simultaneously the gt-CSR end and the pred-region base). Threads then
// process preds in BINNED order, so the 32 lanes of a warp sit in the same /
// adjacent cells: the 3x3-neighborhood loop bounds are near warp-uniform
// (R5/R7's divergence binder) and gt reads broadcast. The pred's original
// index j rides in the payload, so the (gt -> min j) atomicMin semantics are
// unchanged. Equivalence to the full argmin: matches only matter under the
// 16px threshold, and any gt within 16px lies in the 3x3 neighborhood.
// Both ranks atomicMin into RANK 0's s_best (DSMEM for rank 1);
// cluster.sync(); rank 0 does the fused gather.
// d2 uses __fadd_rn/__fmul_rn (no FMA) -> bit-identical to the reference;
// tie rule (equal d2 -> lower gt index) explicit -> order-invariant.
__global__ __launch_bounds__(1024, 1) __cluster_dims__(2, 1, 1)
void lacss_match_kernel(
    const float2* __restrict__ gt,    // [BATCH, NGT]
    const float2* __restrict__ pred,  // [BATCH, MPRED]
    float2* __restrict__ out)         // [BATCH, NGT]
{
    __shared__ int            s_cnt[2 * NCELL];   // counts, then scatter cursor
    __shared__ int            s_off[2 * NCELL + 1];
    __shared__ float4         s_gt[NGT];          // {gx, gy, idx, pad} binned
    __shared__ float2         s_pp[NGT];          // pred coords, binned (per-rank 1024)
    __shared__ unsigned short s_pj[NGT];          // pred original j (< 2048)
    __shared__ int            s_best[NGT];        // min matched pred j per gt (rank0)
    __shared__ int            s_wsum[32];

    cg::cluster_group cluster = cg::this_cluster();
    const unsigned rank = cluster.block_rank();

    const int b    = blockIdx.x >> 1;
    const int tid  = threadIdx.x;
    const int lane = tid & 31;
    const int wid  = tid >> 5;

    // ---- prefetch both inputs (MLP=2, DRAM latency behind binning) ----
    const int j = (int)rank * 1024 + tid;
    const float2 p = pred[b * MPRED + j];
    const float2 g = gt[b * NGT + tid];

    s_cnt[tid]        = 0;
    s_cnt[tid + NGT]  = 0;
    s_best[tid]       = MPRED;           // sentinel: unmatched
    __syncthreads();

    // ---- count both point sets (cell = y/16*32 + x/16; *2^-4 exact) ----
    const int gcell = (int)(g.y * 0.0625f) * GDIM + (int)(g.x * 0.0625f);
    const int pcell = (int)(p.y * 0.0625f) * GDIM + (int)(p.x * 0.0625f);
    atomicAdd(&s_cnt[gcell], 1);
    atomicAdd(&s_cnt[NCELL + pcell], 1);
    __syncthreads();

    // ---- one exclusive prefix sum over the 2048 concatenated counts ----
    const int a0 = s_cnt[2 * tid];
    const int a1 = s_cnt[2 * tid + 1];
    const int v  = a0 + a1;
    int inc = v;
    #pragma unroll
    for (int d = 1; d < 32; d <<= 1) {
        int n = __shfl_up_sync(0xFFFFFFFFu, inc, d);
        if (lane >= d) inc += n;
    }
    if (lane == 31) s_wsum[wid] = inc;
    __syncthreads();
    if (wid == 0) {
        int w  = s_wsum[lane];
        int wi = w;
        #pragma unroll
        for (int d = 1; d < 32; d <<= 1) {
            int n = __shfl_up_sync(0xFFFFFFFFu, wi, d);
            if (lane >= d) wi += n;
        }
        s_wsum[lane] = wi - w;           // exclusive offset of warp `lane`
    }
    __syncthreads();
    const int excl = (inc - v) + s_wsum[wid];
    s_off[2 * tid]     = excl;           // note: s_off[NCELL] == NGT automatically
    s_off[2 * tid + 1] = excl + a0;
    if (tid == 0) s_off[2 * NCELL] = 2 * NGT;
    s_cnt[2 * tid]     = excl;           // cursor = copy of offsets
    s_cnt[2 * tid + 1] = excl + a0;
    __syncthreads();

    // ---- scatter: gts into s_gt[0..1024), preds into s_pp/s_pj ----
    {
        int gpos = atomicAdd(&s_cnt[gcell], 1);
        s_gt[gpos] = make_float4(g.x, g.y, __int_as_float(tid), 0.f);
        int ppos = atomicAdd(&s_cnt[NCELL + pcell], 1) - NGT;  // pred region base = NGT
        s_pp[ppos] = p;
        s_pj[ppos] = (unsigned short)j;
    }
    __syncthreads();

    // ---- scan: thread t handles the t-th BINNED pred (warp-coherent) ----
    {
        const float2 q  = s_pp[tid];
        const int    pj = (int)s_pj[tid];
        const int pcx = (int)(q.x * 0.0625f);
        const int pcy = (int)(q.y * 0.0625f);
        const int x0 = max(pcx - 1, 0), x1 = min(pcx + 1, GDIM - 1);
        const int y0 = max(pcy - 1, 0), y1 = min(pcy + 1, GDIM - 1);

        float best = THRESH2;            // strict < doubles as threshold test
        int   bi   = -1;

        for (int cy = y0; cy <= y1; cy++) {
            const int ks = s_off[cy * GDIM + x0];
            const int ke = s_off[cy * GDIM + x1 + 1];   // cells contiguous in x
            for (int k = ks; k < ke; k++) {
                float4 c = s_gt[k];                     // broadcast LDS.128
                int   gi = __float_as_int(c.z);
                float dx = __fadd_rn(q.x, -c.x);
                float dy = __fadd_rn(q.y, -c.y);
                float d2 = __fadd_rn(__fmul_rn(dx, dx), __fmul_rn(dy, dy));
                bool take = (d2 < best) || (d2 == best && gi < bi);
                bi   = take ? gi : bi;
                best = take ? d2 : best;
            }
        }

        if (bi >= 0) {
            int* dst = (rank == 0) ? s_best
                                   : cluster.map_shared_rank(s_best, 0);
            atomicMin(&dst[bi], pj);
        }
    }

    cluster.sync();                      // orders remote atomics before gather

    // ---- fused gather by rank 0 ----
    if (rank == 0) {
        const int s = s_best[tid];
        out[b * NGT + tid] = (s < MPRED) ? pred[b * MPRED + s] : g;
    }
}

extern "C" void kernel_launch(void* const* d_in, const int* in_sizes, int n_in,
                              void* d_out, int out_size) {
    const float2* gt   = (const float2*)d_in[0];   // gt_locations   [64,1024,2] f32
    const float2* pred = (const float2*)d_in[1];   // pred_locations [64,2048,2] f32
    float2* out = (float2*)d_out;                  // [64,1024,2] f32

    lacss_match_kernel<<<BATCH * 2, 1024>>>(gt, pred, out);
}